// round 3
// baseline (speedup 1.0000x reference)
#include <cuda_runtime.h>
#include <cuda_bf16.h>

#define N_NODES 100000
#define N_EDGES 1600000
#define IN_DIM  512
#define OUT_DIM 32
#define KSTEPS  10
#define ALPHA   0.1f

// ---------------- device scratch (allocation-free) ----------------
__device__ float  g_h[N_NODES * OUT_DIM];      // 12.8 MB
__device__ float  g_z[N_NODES * OUT_DIM];      // 12.8 MB ping buffer
__device__ int    g_src[N_EDGES];
__device__ int    g_dst[N_EDGES];
__device__ int    g_deg[N_NODES];
__device__ float  g_dinv[N_NODES];
__device__ int    g_rowptr[N_NODES + 1];
__device__ int    g_cursor[N_NODES];
__device__ float2 g_packed[N_EDGES];           // {src as int-bits, dinv[src]}
__device__ int    g_partial[128];
__device__ int    g_is64;

// ---------------- dtype sniff: int64 edges have zero high words ----------------
__global__ void k_detect(const int* __restrict__ e32) {
    int ok = 1;
#pragma unroll
    for (int i = 1; i < 64; i += 2)
        if (e32[i] != 0) ok = 0;
    g_is64 = ok;
}

// ---------------- decode edges into int32 src/dst (clamped) ----------------
__global__ void k_decode(const void* __restrict__ ei) {
    int e = blockIdx.x * blockDim.x + threadIdx.x;
    if (e >= N_EDGES) return;
    int s, d;
    if (g_is64) {
        const long long* p = (const long long*)ei;
        s = (int)p[e];
        d = (int)p[N_EDGES + e];
    } else {
        const int* p = (const int*)ei;
        s = p[e];
        d = p[N_EDGES + e];
    }
    if (s < 0) s = 0; if (s >= N_NODES) s = N_NODES - 1;
    if (d < 0) d = 0; if (d >= N_NODES) d = N_NODES - 1;
    g_src[e] = s;
    g_dst[e] = d;
}

// ---------------- degree init (self-loop counted) ----------------
__global__ void k_init_deg() {
    int i = blockIdx.x * blockDim.x + threadIdx.x;
    if (i < N_NODES) g_deg[i] = 1;   // self loop
}

// ---------------- count in-degrees ----------------
__global__ void k_count() {
    int e = blockIdx.x * blockDim.x + threadIdx.x;
    if (e < N_EDGES) atomicAdd(&g_deg[g_dst[e]], 1);
}

// ---------------- dinv = rsqrt(deg) ----------------
__global__ void k_dinv() {
    int i = blockIdx.x * blockDim.x + threadIdx.x;
    if (i < N_NODES) g_dinv[i] = rsqrtf((float)g_deg[i]);
}

// ---------------- scan kernel 1: per-block sums of (deg-1) ----------------
__global__ void k_blocksum() {
    int base = blockIdx.x * 1024;
    int t = threadIdx.x;
    int s = 0;
#pragma unroll
    for (int i = 0; i < 4; i++) {
        int idx = base + t * 4 + i;
        if (idx < N_NODES) s += g_deg[idx] - 1;
    }
#pragma unroll
    for (int o = 16; o; o >>= 1) s += __shfl_down_sync(0xffffffffu, s, o);
    __shared__ int ws[8];
    if ((t & 31) == 0) ws[t >> 5] = s;
    __syncthreads();
    if (t == 0) {
        int tot = 0;
#pragma unroll
        for (int i = 0; i < 8; i++) tot += ws[i];
        g_partial[blockIdx.x] = tot;
    }
}

// ---------------- scan kernel 2: exclusive scan of block sums (1 warp) ----------------
__global__ void k_scanpartial(int nb) {
    int lane = threadIdx.x;
    int v[4];
    int tsum = 0;
#pragma unroll
    for (int i = 0; i < 4; i++) {
        int idx = lane * 4 + i;
        v[i] = (idx < nb) ? g_partial[idx] : 0;
        tsum += v[i];
    }
    int inc = tsum;
#pragma unroll
    for (int o = 1; o < 32; o <<= 1) {
        int y = __shfl_up_sync(0xffffffffu, inc, o);
        if (lane >= o) inc += y;
    }
    int run = inc - tsum;   // exclusive
#pragma unroll
    for (int i = 0; i < 4; i++) {
        int idx = lane * 4 + i;
        if (idx < nb) { g_partial[idx] = run; run += v[i]; }
    }
    int total = __shfl_sync(0xffffffffu, inc, 31);
    if (lane == 0) g_rowptr[N_NODES] = total;
}

// ---------------- scan kernel 3: full exclusive scan -> rowptr & cursor ----------------
__global__ void k_blockscan() {
    int t = threadIdx.x;
    int base = blockIdx.x * 1024 + t * 4;
    int v[4];
    int tsum = 0;
#pragma unroll
    for (int i = 0; i < 4; i++) {
        int idx = base + i;
        v[i] = (idx < N_NODES) ? (g_deg[idx] - 1) : 0;
        tsum += v[i];
    }
    int lane = t & 31, warp = t >> 5;
    int inc = tsum;
#pragma unroll
    for (int o = 1; o < 32; o <<= 1) {
        int y = __shfl_up_sync(0xffffffffu, inc, o);
        if (lane >= o) inc += y;
    }
    int excl = inc - tsum;
    __shared__ int wtot[8];
    if (lane == 31) wtot[warp] = inc;
    __syncthreads();
    if (t == 0) {
        int acc = 0;
#pragma unroll
        for (int i = 0; i < 8; i++) { int x = wtot[i]; wtot[i] = acc; acc += x; }
    }
    __syncthreads();
    int off = g_partial[blockIdx.x] + wtot[warp] + excl;
#pragma unroll
    for (int i = 0; i < 4; i++) {
        int idx = base + i;
        if (idx < N_NODES) { g_rowptr[idx] = off; g_cursor[idx] = off; off += v[i]; }
    }
}

// ---------------- CSR scatter ----------------
__global__ void k_scatter() {
    int e = blockIdx.x * blockDim.x + threadIdx.x;
    if (e >= N_EDGES) return;
    int s = g_src[e];
    int d = g_dst[e];
    int pos = atomicAdd(&g_cursor[d], 1);
    g_packed[pos] = make_float2(__int_as_float(s), g_dinv[s]);
}

// ---------------- dense projection: h = x @ W^T + b ----------------
__global__ void k_gemm(const float* __restrict__ x, const float* __restrict__ W,
                       const float* __restrict__ b) {
    __shared__ float Wsm[256 * 33];   // 33792 B
    int lane = threadIdx.x & 31;
    int warp = threadIdx.x >> 5;
    int row0 = (blockIdx.x * 8 + warp) * 4;
    const float* xr = x + (size_t)row0 * IN_DIM;

    float acc0 = 0.f, acc1 = 0.f, acc2 = 0.f, acc3 = 0.f;

    for (int p = 0; p < 2; p++) {
        __syncthreads();
        for (int idx = threadIdx.x; idx < 8192; idx += 256) {
            int j  = idx >> 8;     // 0..31
            int kl = idx & 255;    // 0..255
            Wsm[kl * 33 + j] = W[j * IN_DIM + p * 256 + kl];
        }
        __syncthreads();
#pragma unroll 1
        for (int cl = 0; cl < 8; cl++) {
            int c = p * 8 + cl;
            float xa = xr[c * 32 + lane];
            float xb = xr[512 + c * 32 + lane];
            float xc = xr[1024 + c * 32 + lane];
            float xd = xr[1536 + c * 32 + lane];
#pragma unroll
            for (int kk = 0; kk < 32; kk++) {
                float w = Wsm[(cl * 32 + kk) * 33 + lane];
                acc0 = fmaf(__shfl_sync(0xffffffffu, xa, kk), w, acc0);
                acc1 = fmaf(__shfl_sync(0xffffffffu, xb, kk), w, acc1);
                acc2 = fmaf(__shfl_sync(0xffffffffu, xc, kk), w, acc2);
                acc3 = fmaf(__shfl_sync(0xffffffffu, xd, kk), w, acc3);
            }
        }
    }
    float bv = b[lane];
    float* hp = g_h + (size_t)row0 * OUT_DIM;
    hp[lane]      = acc0 + bv;
    hp[32 + lane] = acc1 + bv;
    hp[64 + lane] = acc2 + bv;
    hp[96 + lane] = acc3 + bv;
}

// ---------------- propagation step (pull, warp per node, lane = out dim) ----------------
__global__ void k_prop(int srcSel, int dstSel, float* __restrict__ dout) {
    int gw   = (blockIdx.x * blockDim.x + threadIdx.x) >> 5;
    int lane = threadIdx.x & 31;
    const float* zin = (srcSel == 0) ? g_h : (srcSel == 1) ? g_z : dout;
    float* zout = (dstSel == 1) ? g_z : dout;

    int start = g_rowptr[gw];
    int end   = g_rowptr[gw + 1];

    float acc = 0.f, accB = 0.f;
    for (int base = start; base < end; base += 32) {
        int m = end - base;
        if (m > 32) m = 32;
        float2 p = make_float2(0.f, 0.f);
        if (lane < m) p = g_packed[base + lane];
        int   si = __float_as_int(p.x);
        float wi = p.y;
        int kk = 0;
        for (; kk + 4 <= m; kk += 4) {
            int s0 = __shfl_sync(0xffffffffu, si, kk);
            int s1 = __shfl_sync(0xffffffffu, si, kk + 1);
            int s2 = __shfl_sync(0xffffffffu, si, kk + 2);
            int s3 = __shfl_sync(0xffffffffu, si, kk + 3);
            float w0 = __shfl_sync(0xffffffffu, wi, kk);
            float w1 = __shfl_sync(0xffffffffu, wi, kk + 1);
            float w2 = __shfl_sync(0xffffffffu, wi, kk + 2);
            float w3 = __shfl_sync(0xffffffffu, wi, kk + 3);
            float z0 = zin[s0 * 32 + lane];
            float z1 = zin[s1 * 32 + lane];
            float z2 = zin[s2 * 32 + lane];
            float z3 = zin[s3 * 32 + lane];
            acc  = fmaf(w0, z0, acc);
            accB = fmaf(w1, z1, accB);
            acc  = fmaf(w2, z2, acc);
            accB = fmaf(w3, z3, accB);
        }
        for (; kk < m; kk++) {
            int   s = __shfl_sync(0xffffffffu, si, kk);
            float w = __shfl_sync(0xffffffffu, wi, kk);
            acc = fmaf(w, zin[s * 32 + lane], acc);
        }
    }
    float di = g_dinv[gw];
    float zi = zin[gw * 32 + lane];
    float agg = di * fmaf(di, zi, acc + accB);
    zout[gw * 32 + lane] = (1.0f - ALPHA) * agg + ALPHA * g_h[gw * 32 + lane];
}

// ---------------- host launcher ----------------
extern "C" void kernel_launch(void* const* d_in, const int* in_sizes, int n_in,
                              void* d_out, int out_size) {
    const float* x  = (const float*)d_in[0];
    const float* W  = (const float*)d_in[1];
    const float* b  = (const float*)d_in[2];
    const void*  ei = d_in[3];
    float* out = (float*)d_out;

    const int NB = (N_NODES + 1023) / 1024;   // 98

    k_detect<<<1, 1>>>((const int*)ei);
    k_decode<<<(N_EDGES + 255) / 256, 256>>>(ei);
    k_init_deg<<<(N_NODES + 255) / 256, 256>>>();
    k_count<<<N_EDGES / 256, 256>>>();
    k_dinv<<<(N_NODES + 255) / 256, 256>>>();
    k_blocksum<<<NB, 256>>>();
    k_scanpartial<<<1, 32>>>(NB);
    k_blockscan<<<NB, 256>>>();
    k_scatter<<<N_EDGES / 256, 256>>>();
    k_gemm<<<N_NODES / 32, 256>>>(x, W, b);

    // step 1 reads h, writes g_z; even steps write dout; odd steps (>=3) write g_z.
    k_prop<<<N_NODES * 32 / 256, 256>>>(0, 1, out);
    for (int s = 2; s <= KSTEPS; s++) {
        if ((s & 1) == 0) k_prop<<<N_NODES * 32 / 256, 256>>>(1, 2, out);
        else              k_prop<<<N_NODES * 32 / 256, 256>>>(2, 1, out);
    }
}